// round 13
// baseline (speedup 1.0000x reference)
#include <cuda_runtime.h>
#include <cuda_fp16.h>
#include <cstdint>

#define N_TOK   65536
#define DIM     256
#define NC      4096
#define QELEMS  ((size_t)N_TOK * DIM)

#define M_CTA    64
#define NCHUNK   128
#define NSPLIT   2
#define NC_S     (NC / NSPLIT)          // 2048 codes per split CTA
#define NCHUNKS_S (NC_S / NCHUNK)       // 16
#define TOTJ_S   (NCHUNKS_S * 4)        // 64 k-block steps
#define NTILES   (N_TOK / M_CTA)        // 1024
#define K1_GRID  (NTILES * NSPLIT)      // 2048
#define MARGIN   0.03f

// K1 dynamic smem layout (bytes) — sized for 3 CTAs/SM
#define SM_CN    0                       // 2048 f32 (split half) = 8192
#define SM_A     8192                    // 64x256 fp16 = 32768 (4 kb x 8192)
#define SM_B     (SM_A + 32768)          // 2 stages x 16KB = 32768
#define SMEM_TOTAL (SM_B + 32768)        // 73728  (3/SM: 221KB <= 228KB)

// fixup dynamic smem: 3-stage Es ring (512 codes/task) + Xs + small
#define FX_ES     0                      // 3 x 8 x 512 f32 = 49152
#define FX_XS     49152                  // 8 x 256 f32 = 8192
#define FX_TOKS   (FX_XS + 8192)         // 8 ints
#define FX_WB     (FX_TOKS + 32)         // 8x8 f32
#define FX_WI     (FX_WB + 256)          // 8x8 int
#define FX_SMEM   (FX_WI + 256)          // 57888
#define FX_GRID   1184

// -------------------- scratch ----------------------------------------------
__device__ __half g_ebh[(size_t)NC * DIM];          // fp16 codebook [code][dim]
__device__ __half g_xh[(size_t)N_TOK * DIM];        // fp16 x, pre-swizzled per tile
__device__ float  g_embedT[(size_t)NC * DIM];       // fp32 codebook [code][dim]
__device__ float  g_cnh[NC];                        // 0.5*||e||^2
__device__ int    g_idx[N_TOK];                     // winner; ~i if flagged
__device__ float  g_partials[N_TOK / 8];            // per-CTA diff partials
__device__ int    g_count;
__device__ int    g_list[N_TOK];
__device__ unsigned long long g_best[N_TOK];
// per-split K1 results
__device__ float  g_hb[NSPLIT * N_TOK];
__device__ float  g_hs[NSPLIT * N_TOK];
__device__ int    g_hi[NSPLIT * N_TOK];

// -------------------- helpers ----------------------------------------------
__device__ __forceinline__ uint32_t smem_u32(const void* p) {
    uint32_t a;
    asm("{ .reg .u64 t; cvta.to.shared.u64 t, %1; cvt.u32.u64 %0, t; }"
        : "=r"(a) : "l"(p));
    return a;
}
__device__ __forceinline__ uint32_t swz(uint32_t b) { return b ^ ((b >> 3) & 0x70); }

__device__ __forceinline__ void ldsm4(uint32_t* r, uint32_t a) {
    asm volatile("ldmatrix.sync.aligned.m8n8.x4.shared.b16 {%0,%1,%2,%3}, [%4];"
        : "=r"(r[0]), "=r"(r[1]), "=r"(r[2]), "=r"(r[3]) : "r"(a));
}
__device__ __forceinline__ void mma16816(float* c, const uint32_t* a, const uint32_t* b) {
    asm volatile("mma.sync.aligned.m16n8k16.row.col.f32.f16.f16.f32 "
        "{%0,%1,%2,%3}, {%4,%5,%6,%7}, {%8,%9}, {%0,%1,%2,%3};"
        : "+f"(c[0]), "+f"(c[1]), "+f"(c[2]), "+f"(c[3])
        : "r"(a[0]), "r"(a[1]), "r"(a[2]), "r"(a[3]), "r"(b[0]), "r"(b[1]));
}
__device__ __forceinline__ void cpa16(uint32_t s, const void* g) {
    asm volatile("cp.async.cg.shared.global [%0], [%1], 16;" :: "r"(s), "l"(g));
}
#define CP_COMMIT() asm volatile("cp.async.commit_group;" ::: "memory")
#define CP_WAIT1()  asm volatile("cp.async.wait_group 1;" ::: "memory")
#define CP_WAIT0()  asm volatile("cp.async.wait_group 0;" ::: "memory")

// monotonic (score, smaller-idx-wins) packing for atomicMax merge
__device__ __forceinline__ unsigned long long pack_si(float s, int idx) {
    uint32_t u = __float_as_uint(s);
    u = (s < 0.0f) ? ~u : (u | 0x80000000u);
    return ((unsigned long long)u << 32) | (uint32_t)(NC - 1 - idx);
}

// ---------------------------------------------------------------------------
// K0a: transpose codebook + fp16 cast; zero compaction counter
// ---------------------------------------------------------------------------
__global__ void prep_transpose(const float* __restrict__ embed) {
    __shared__ float ts[64][65];
    if (blockIdx.x == 0 && blockIdx.y == 0 && threadIdx.x == 0) g_count = 0;
    int c0 = blockIdx.x * 64, d0 = blockIdx.y * 64;
    int a = threadIdx.x & 63, b = threadIdx.x >> 6;
    #pragma unroll
    for (int i = 0; i < 16; ++i) {
        int d = b + i * 4;
        ts[d][a] = embed[(size_t)(d0 + d) * NC + c0 + a];
    }
    __syncthreads();
    #pragma unroll
    for (int i = 0; i < 16; ++i) {
        int cI = b + i * 4;
        float v = ts[a][cI];
        size_t o = (size_t)(c0 + cI) * DIM + d0 + a;
        g_embedT[o] = v;
        g_ebh[o] = __float2half_rn(v);
    }
}

// ---------------------------------------------------------------------------
// K0b: 0.5*||e||^2
// ---------------------------------------------------------------------------
__global__ void prep_cnorm(void) {
    int w = threadIdx.x >> 5, l = threadIdx.x & 31;
    int c = blockIdx.x * 8 + w;
    const float4* er = reinterpret_cast<const float4*>(g_embedT + (size_t)c * DIM);
    float4 p = er[l], q = er[l + 32];
    float s = p.x*p.x + p.y*p.y + p.z*p.z + p.w*p.w
            + q.x*q.x + q.y*q.y + q.z*q.z + q.w*q.w;
    #pragma unroll
    for (int off = 16; off; off >>= 1) s += __shfl_down_sync(0xffffffffu, s, off);
    if (l == 0) g_cnh[c] = 0.5f * s;
}

// ---------------------------------------------------------------------------
// K0c: convert x -> fp16, pre-swizzled per 64-token tile (SM_A layout).
// ---------------------------------------------------------------------------
__global__ __launch_bounds__(256)
void prep_xconv(const float* __restrict__ x) {
    const int tile = blockIdx.x;
    const int w = threadIdx.x >> 5, l = threadIdx.x & 31;
    uint32_t* dst = reinterpret_cast<uint32_t*>(g_xh) + (size_t)tile * 8192;
    #pragma unroll
    for (int i = 0; i < 8; ++i) {
        int r = w + i * 8;
        const float2* xr2 = reinterpret_cast<const float2*>(
            x + ((size_t)tile * M_CTA + r) * DIM);
        #pragma unroll
        for (int kb = 0; kb < 4; ++kb) {
            float2 v = xr2[kb * 32 + l];
            __half h0 = __float2half_rn(v.x), h1 = __float2half_rn(v.y);
            uint32_t p = ((uint32_t)__half_as_ushort(h1) << 16) | __half_as_ushort(h0);
            dst[(kb * 8192 + swz((uint32_t)(r * 128 + l * 4))) >> 2] = p;
        }
    }
}

// ---------------------------------------------------------------------------
// K1: fp16 HMMA GEMM + per-split top-2 argmax.
//     CTA = (64 tokens) x (2048 codes), 3 CTAs/SM, warp tile 16x64.
// ---------------------------------------------------------------------------
__global__ __launch_bounds__(256, 3)
void vq_hmma(void) {
    extern __shared__ char smem[];
    const uint32_t sbase = smem_u32(smem);
    const int tid = threadIdx.x, lane = tid & 31, wid = tid >> 5;
    const int warp_m = wid & 3, warp_n = wid >> 2;   // 4 x 2
    const int tileId = blockIdx.x >> 1, split = blockIdx.x & 1;
    const int tokBase = tileId * M_CTA;
    const int codeBase = split * NC_S;

    // split-local cnorm half -> smem
    {
        float4* cs = reinterpret_cast<float4*>(smem + SM_CN);
        const float4* cg = reinterpret_cast<const float4*>(g_cnh + codeBase);
        cs[tid] = cg[tid];
        cs[tid + 256] = cg[tid + 256];
    }

    const int seg = tid & 7, rb = tid >> 3;

    auto loadB = [&](int j) {
        int c0 = codeBase + (j >> 2) * NCHUNK, kb = j & 3;
        uint32_t bb = sbase + SM_B + (j & 1) * 16384;
        #pragma unroll
        for (int i = 0; i < 4; ++i) {
            int row = rb + 32 * i;
            size_t go = ((size_t)(c0 + row) << 8) + kb * 64 + seg * 8;
            uint32_t so = swz((uint32_t)(row * 128 + seg * 16));
            cpa16(bb + so, g_ebh + go);
        }
    };

    // A tile: straight 32KB async copy of pre-swizzled fp16
    {
        const char* asrc = reinterpret_cast<const char*>(g_xh) + (size_t)tileId * 32768;
        #pragma unroll
        for (int k = 0; k < 8; ++k)
            cpa16(sbase + SM_A + tid * 16 + k * 4096, asrc + tid * 16 + k * 4096);
    }
    loadB(0); CP_COMMIT();
    loadB(1); CP_COMMIT();

    float acc[8][4];
    float best[2], sec[2];
    int   bi[2];
    #pragma unroll
    for (int i = 0; i < 2; ++i) { best[i] = -1e30f; sec[i] = -1e30f; bi[i] = 0; }

    const float* cnh = reinterpret_cast<const float*>(smem + SM_CN);
    const int r16 = lane & 15, cg8 = (lane >> 4) << 3;

    for (int j = 0; j < TOTJ_S; ++j) {
        if (j + 1 < TOTJ_S) CP_WAIT1(); else CP_WAIT0();
        __syncthreads();                 // stage j (and A on j=0) landed CTA-wide

        const int kb = j & 3;
        const uint32_t aB = sbase + SM_A + kb * 8192;
        const uint32_t bB = sbase + SM_B + (j & 1) * 16384;

        if (kb == 0) {
            #pragma unroll
            for (int nt = 0; nt < 8; ++nt)
                #pragma unroll
                for (int e = 0; e < 4; ++e) acc[nt][e] = 0.0f;
        }

        #pragma unroll
        for (int ks = 0; ks < 4; ++ks) {
            const int kcol = ks * 16 + cg8;
            uint32_t ah[4], bh[8][2];
            {
                uint32_t off = swz((uint32_t)((warp_m * 16 + r16) * 128 + kcol * 2));
                ldsm4(ah, aB + off);
            }
            #pragma unroll
            for (int p = 0; p < 4; ++p) {
                uint32_t off = swz((uint32_t)((warp_n * 64 + p * 16 + r16) * 128 + kcol * 2));
                uint32_t t[4];
                ldsm4(t, bB + off);
                bh[2*p][0]   = t[0]; bh[2*p][1]   = t[2];
                bh[2*p+1][0] = t[1]; bh[2*p+1][1] = t[3];
            }
            #pragma unroll
            for (int nt = 0; nt < 8; ++nt)
                mma16816(acc[nt], ah, bh[nt]);
        }

        if (kb == 3) {
            const int cl0 = (j >> 2) * NCHUNK + warp_n * 64 + (lane & 3) * 2;
            #pragma unroll
            for (int nt = 0; nt < 8; ++nt) {
                const int c0 = cl0 + nt * 8;
                const float cn0 = cnh[c0], cn1 = cnh[c0 + 1];
                float v;
                v = acc[nt][0] - cn0;
                if (v > best[0]) { sec[0] = best[0]; best[0] = v; bi[0] = c0; }
                else if (v > sec[0]) sec[0] = v;
                v = acc[nt][1] - cn1;
                if (v > best[0]) { sec[0] = best[0]; best[0] = v; bi[0] = c0 + 1; }
                else if (v > sec[0]) sec[0] = v;
                v = acc[nt][2] - cn0;
                if (v > best[1]) { sec[1] = best[1]; best[1] = v; bi[1] = c0; }
                else if (v > sec[1]) sec[1] = v;
                v = acc[nt][3] - cn1;
                if (v > best[1]) { sec[1] = best[1]; best[1] = v; bi[1] = c0 + 1; }
                else if (v > sec[1]) sec[1] = v;
            }
        }

        __syncthreads();                 // all warps done reading stage j's buffer
        if (j + 2 < TOTJ_S) { loadB(j + 2); CP_COMMIT(); }
    }
    __syncthreads();                     // SM_B reusable for merge

    // intra-quad top-2 merge (lanes 0-3 share a row)
    #pragma unroll
    for (int s = 0; s < 2; ++s) {
        float b = best[s], se = sec[s];
        int   i = bi[s];
        #pragma unroll
        for (int off = 1; off <= 2; off <<= 1) {
            float ob = __shfl_xor_sync(0xffffffffu, b, off);
            float os = __shfl_xor_sync(0xffffffffu, se, off);
            int   oi = __shfl_xor_sync(0xffffffffu, i, off);
            if (ob > b || (ob == b && oi < i)) { se = fmaxf(b, os); b = ob; i = oi; }
            else                               { se = fmaxf(se, ob); }
        }
        best[s] = b; sec[s] = se; bi[s] = i;
    }

    float* mb = reinterpret_cast<float*>(smem + SM_B);
    float* ms = mb + 64;
    int*   mi = reinterpret_cast<int*>(ms + 64);
    if (warp_n == 0 && (lane & 3) == 0) {
        #pragma unroll
        for (int s = 0; s < 2; ++s) {
            int row = warp_m * 16 + s * 8 + (lane >> 2);
            mb[row] = best[s]; ms[row] = sec[s]; mi[row] = bi[s];
        }
    }
    __syncthreads();
    if (warp_n == 1 && (lane & 3) == 0) {
        #pragma unroll
        for (int s = 0; s < 2; ++s) {
            int row = warp_m * 16 + s * 8 + (lane >> 2);
            float b = best[s], se = sec[s];
            int   i = bi[s];
            float ob = mb[row], os = ms[row];
            int   oi = mi[row];
            if (ob > b || (ob == b && oi < i)) { se = fmaxf(b, os); b = ob; i = oi; }
            else                               { se = fmaxf(se, ob); }
            size_t o = (size_t)split * N_TOK + tokBase + row;
            g_hb[o] = b; g_hs[o] = se; g_hi[o] = codeBase + i;
        }
    }
}

// ---------------------------------------------------------------------------
// K1b: merge the two code-half results -> winner, margin flag, compaction
// ---------------------------------------------------------------------------
__global__ void merge_halves(void) {
    int t = blockIdx.x * 256 + threadIdx.x;
    float b0 = g_hb[t], b1 = g_hb[N_TOK + t];
    float s0 = g_hs[t], s1 = g_hs[N_TOK + t];
    int   i0 = g_hi[t], i1 = g_hi[N_TOK + t];
    float b, se; int i;
    if (b1 > b0 || (b1 == b0 && i1 < i0)) { b = b1; i = i1; se = fmaxf(s1, b0); }
    else                                  { b = b0; i = i0; se = fmaxf(s0, b1); }
    if (b - se < MARGIN) {
        g_idx[t]  = ~i;
        g_best[t] = 0ULL;
        int p = atomicAdd(&g_count, 1);
        g_list[p] = t;
    } else {
        g_idx[t] = i;
    }
}

// ---------------------------------------------------------------------------
// K2: exact fp32 rescore — persistent grid. Task = (8 tokens) x (512 codes).
// ---------------------------------------------------------------------------
__global__ __launch_bounds__(256)
void fixup_micro(const float* __restrict__ x, const float* __restrict__ embed) {
    extern __shared__ char fsm[];
    const uint32_t fbase = smem_u32(fsm);
    float (*Es)[8][512] = reinterpret_cast<float(*)[8][512]>(fsm + FX_ES);
    float (*Xs)[256]    = reinterpret_cast<float(*)[256]>(fsm + FX_XS);
    int*   toks         = reinterpret_cast<int*>(fsm + FX_TOKS);
    float (*wb)[8]      = reinterpret_cast<float(*)[8]>(fsm + FX_WB);
    int   (*wi)[8]      = reinterpret_cast<int(*)[8]>(fsm + FX_WI);

    const int tid = threadIdx.x, lane = tid & 31, wid = tid >> 5;
    const int cnt = g_count;
    const int nTasks = ((cnt + 7) >> 3) * 8;

    for (int task = blockIdx.x; task < nTasks; task += FX_GRID) {
        const int grp = task >> 3, part = task & 7;
        const int cbase = part * 512;

        __syncthreads();                 // protect smem reuse across tasks
        if (tid < 8) {
            int li = grp * 8 + tid;
            toks[tid] = g_list[li < cnt ? li : 0];
        }
        __syncthreads();
        {
            int tk = tid & 7, d0 = (tid >> 3) * 8;
            const float* xr = x + (size_t)toks[tk] * DIM + d0;
            #pragma unroll
            for (int i = 0; i < 8; ++i) Xs[tk][d0 + i] = xr[i];
        }

        auto loadE = [&](int s) {
            uint32_t dst = fbase + FX_ES + (s % 3) * 16384 + wid * 2048 + lane * 16;
            const float* src = embed + (size_t)(s * 8 + wid) * NC + cbase + lane * 4;
            #pragma unroll
            for (int r = 0; r < 4; ++r) cpa16(dst + r * 512, src + r * 128);
        };
        loadE(0); CP_COMMIT();
        loadE(1); CP_COMMIT();

        float acc[8][2];
        #pragma unroll
        for (int t = 0; t < 8; ++t) { acc[t][0] = 0.0f; acc[t][1] = 0.0f; }

        for (int s = 0; s < 32; ++s) {
            if (s < 30) CP_WAIT1(); else CP_WAIT0();
            __syncthreads();
            if (s + 2 < 32) { loadE(s + 2); CP_COMMIT(); }

            const int buf = s % 3;
            #pragma unroll
            for (int h = 0; h < 2; ++h) {
                float4 xq[8];
                #pragma unroll
                for (int t = 0; t < 8; ++t)
                    xq[t] = *reinterpret_cast<const float4*>(&Xs[t][s * 8 + h * 4]);
                #pragma unroll
                for (int k2 = 0; k2 < 4; ++k2) {
                    float2 e2 = *reinterpret_cast<const float2*>(
                        &Es[buf][h * 4 + k2][tid * 2]);
                    #pragma unroll
                    for (int t = 0; t < 8; ++t) {
                        float xv = (k2 == 0) ? xq[t].x : (k2 == 1) ? xq[t].y
                                 : (k2 == 2) ? xq[t].z : xq[t].w;
                        acc[t][0] = fmaf(xv, e2.x, acc[t][0]);
                        acc[t][1] = fmaf(xv, e2.y, acc[t][1]);
                    }
                }
            }
        }

        float best[8]; int bi[8];
        #pragma unroll
        for (int t = 0; t < 8; ++t) { best[t] = -1e30f; bi[t] = 0; }
        #pragma unroll
        for (int jj = 0; jj < 2; ++jj) {
            int c = cbase + tid * 2 + jj;
            float cn = g_cnh[c];
            #pragma unroll
            for (int t = 0; t < 8; ++t) {
                float s = acc[t][jj] - cn;
                if (s > best[t]) { best[t] = s; bi[t] = c; }
            }
        }

        #pragma unroll
        for (int t = 0; t < 8; ++t) {
            float b = best[t]; int i = bi[t];
            #pragma unroll
            for (int off = 16; off; off >>= 1) {
                float ob = __shfl_down_sync(0xffffffffu, b, off);
                int   oi = __shfl_down_sync(0xffffffffu, i, off);
                if (ob > b || (ob == b && oi < i)) { b = ob; i = oi; }
            }
            if (lane == 0) { wb[wid][t] = b; wi[wid][t] = i; }
        }
        __syncthreads();
        if (wid == 0 && lane < 8) {
            int t = lane;
            float b = wb[0][t]; int i = wi[0][t];
            #pragma unroll
            for (int w = 1; w < 8; ++w) {
                float ob = wb[w][t]; int oi = wi[w][t];
                if (ob > b || (ob == b && oi < i)) { b = ob; i = oi; }
            }
            atomicMax(&g_best[toks[t]], pack_si(b, i));
        }
    }
}

// ---------------------------------------------------------------------------
// K3: gather quantize + per-CTA diff partial + indices (warp per token)
// ---------------------------------------------------------------------------
__global__ __launch_bounds__(256)
void quantize_kernel(const float* __restrict__ x, float* __restrict__ out) {
    __shared__ float swred[8];
    int gt = blockIdx.x * 8 + (threadIdx.x >> 5);
    int l = threadIdx.x & 31, wid = threadIdx.x >> 5;
    int idx = g_idx[gt];
    if (idx < 0)
        idx = NC - 1 - (int)(uint32_t)(g_best[gt] & 0xFFFFFFFFULL);
    const float4* er = reinterpret_cast<const float4*>(g_embedT + (size_t)idx * DIM);
    const float4* xr = reinterpret_cast<const float4*>(x + (size_t)gt * DIM);
    float4* qw = reinterpret_cast<float4*>(out + (size_t)gt * DIM);
    float s = 0.0f;
    #pragma unroll
    for (int i = 0; i < 2; ++i) {
        int k = l + 32 * i;
        float4 q = er[k], xv = xr[k];
        float d0 = q.x - xv.x, d1 = q.y - xv.y, d2 = q.z - xv.z, d3 = q.w - xv.w;
        s = fmaf(d0, d0, s); s = fmaf(d1, d1, s);
        s = fmaf(d2, d2, s); s = fmaf(d3, d3, s);
        qw[k] = q;
    }
    #pragma unroll
    for (int off = 16; off; off >>= 1) s += __shfl_down_sync(0xffffffffu, s, off);
    if (l == 0) {
        swred[wid] = s;
        out[QELEMS + 1 + (size_t)gt] = (float)idx;
    }
    __syncthreads();
    if (threadIdx.x == 0) {
        float tot = 0.0f;
        #pragma unroll
        for (int w = 0; w < 8; ++w) tot += swred[w];
        g_partials[blockIdx.x] = tot;
    }
}

// ---------------------------------------------------------------------------
// K4: deterministic diff reduction (8192 per-CTA partials)
// ---------------------------------------------------------------------------
__global__ void finalize_kernel(float* __restrict__ out) {
    __shared__ float sh[256];
    int tid = threadIdx.x;
    const float4* p4 = reinterpret_cast<const float4*>(g_partials);
    float s = 0.0f;
    #pragma unroll
    for (int j = 0; j < 8; ++j) {
        float4 v = p4[tid + 256 * j];
        s += v.x + v.y + v.z + v.w;
    }
    sh[tid] = s;
    __syncthreads();
    for (int off = 128; off; off >>= 1) {
        if (tid < off) sh[tid] += sh[tid + off];
        __syncthreads();
    }
    if (tid == 0) out[QELEMS] = sh[0] / (float)QELEMS;
}

// ---------------------------------------------------------------------------
extern "C" void kernel_launch(void* const* d_in, const int* in_sizes, int n_in,
                              void* d_out, int out_size) {
    const float* x     = (const float*)d_in[0];
    const float* embed = (const float*)d_in[1];
    float* out = (float*)d_out;

    cudaFuncSetAttribute(vq_hmma, cudaFuncAttributeMaxDynamicSharedMemorySize,
                         SMEM_TOTAL);
    cudaFuncSetAttribute(fixup_micro, cudaFuncAttributeMaxDynamicSharedMemorySize,
                         FX_SMEM);

    prep_transpose<<<dim3(NC / 64, DIM / 64), 256>>>(embed);
    prep_cnorm<<<NC / 8, 256>>>();
    prep_xconv<<<NTILES, 256>>>(x);
    vq_hmma<<<K1_GRID, 256, SMEM_TOTAL>>>();
    merge_halves<<<N_TOK / 256, 256>>>();
    fixup_micro<<<FX_GRID, 256, FX_SMEM>>>(x, embed);
    quantize_kernel<<<N_TOK / 8, 256>>>(x, out);
    finalize_kernel<<<1, 256>>>(out);
}

// round 14
// speedup vs baseline: 1.0419x; 1.0419x over previous
#include <cuda_runtime.h>
#include <cuda_fp16.h>
#include <cstdint>

#define N_TOK   65536
#define DIM     256
#define NC      4096
#define QELEMS  ((size_t)N_TOK * DIM)

#define M_CTA    128
#define NCHUNK   128
#define NSPLIT   2
#define NC_S     (NC / NSPLIT)          // 2048 codes per split CTA
#define NCHUNKS_S (NC_S / NCHUNK)       // 16
#define TOTJ_S   (NCHUNKS_S * 4)        // 64 k-block steps
#define NTILES   (N_TOK / M_CTA)        // 512
#define K1_GRID  (NTILES * NSPLIT)      // 1024
#define MARGIN   0.03f

// K1 dynamic smem layout (bytes) — A + 3-stage B ring, 2 CTAs/SM
#define SM_A     0                       // 128x256 fp16 = 65536
#define SM_B     65536                   // 3 stages x 16KB = 49152
#define SMEM_TOTAL (SM_B + 49152)        // 114688 (2/SM: 224KB <= 228KB)

// fixup dynamic smem: 3-stage Es ring (512 codes/task) + Xs + small
#define FX_ES     0                      // 3 x 8 x 512 f32 = 49152
#define FX_XS     49152                  // 8 x 256 f32 = 8192
#define FX_TOKS   (FX_XS + 8192)         // 8 ints
#define FX_WB     (FX_TOKS + 32)         // 8x8 f32
#define FX_WI     (FX_WB + 256)          // 8x8 int
#define FX_SMEM   (FX_WI + 256)          // 57888
#define FX_GRID   1184

// -------------------- scratch ----------------------------------------------
__device__ __half g_ebh[(size_t)NC * DIM];          // fp16 codebook [code][dim]
__device__ __half g_xh[(size_t)N_TOK * DIM];        // fp16 x, pre-swizzled per tile
__device__ float  g_embedT[(size_t)NC * DIM];       // fp32 codebook [code][dim]
__device__ float  g_cnh[NC];                        // 0.5*||e||^2
__device__ int    g_idx[N_TOK];                     // winner; ~i if flagged
__device__ float  g_partials[N_TOK / 8];            // per-CTA diff partials
__device__ int    g_count;
__device__ int    g_list[N_TOK];
__device__ unsigned long long g_best[N_TOK];
// per-split K1 results
__device__ float  g_hb[NSPLIT * N_TOK];
__device__ float  g_hs[NSPLIT * N_TOK];
__device__ int    g_hi[NSPLIT * N_TOK];

// -------------------- helpers ----------------------------------------------
__device__ __forceinline__ uint32_t smem_u32(const void* p) {
    uint32_t a;
    asm("{ .reg .u64 t; cvta.to.shared.u64 t, %1; cvt.u32.u64 %0, t; }"
        : "=r"(a) : "l"(p));
    return a;
}
__device__ __forceinline__ uint32_t swz(uint32_t b) { return b ^ ((b >> 3) & 0x70); }

__device__ __forceinline__ void ldsm4(uint32_t* r, uint32_t a) {
    asm volatile("ldmatrix.sync.aligned.m8n8.x4.shared.b16 {%0,%1,%2,%3}, [%4];"
        : "=r"(r[0]), "=r"(r[1]), "=r"(r[2]), "=r"(r[3]) : "r"(a));
}
__device__ __forceinline__ void mma16816(float* c, const uint32_t* a, const uint32_t* b) {
    asm volatile("mma.sync.aligned.m16n8k16.row.col.f32.f16.f16.f32 "
        "{%0,%1,%2,%3}, {%4,%5,%6,%7}, {%8,%9}, {%0,%1,%2,%3};"
        : "+f"(c[0]), "+f"(c[1]), "+f"(c[2]), "+f"(c[3])
        : "r"(a[0]), "r"(a[1]), "r"(a[2]), "r"(a[3]), "r"(b[0]), "r"(b[1]));
}
__device__ __forceinline__ void cpa16(uint32_t s, const void* g) {
    asm volatile("cp.async.cg.shared.global [%0], [%1], 16;" :: "r"(s), "l"(g));
}
#define CP_COMMIT() asm volatile("cp.async.commit_group;" ::: "memory")
#define CP_WAIT1()  asm volatile("cp.async.wait_group 1;" ::: "memory")
#define CP_WAIT0()  asm volatile("cp.async.wait_group 0;" ::: "memory")

// monotonic (score, smaller-idx-wins) packing for atomicMax merge
__device__ __forceinline__ unsigned long long pack_si(float s, int idx) {
    uint32_t u = __float_as_uint(s);
    u = (s < 0.0f) ? ~u : (u | 0x80000000u);
    return ((unsigned long long)u << 32) | (uint32_t)(NC - 1 - idx);
}

// ---------------------------------------------------------------------------
// K0a: transpose codebook + fp16 cast; zero compaction counter
// ---------------------------------------------------------------------------
__global__ void prep_transpose(const float* __restrict__ embed) {
    __shared__ float ts[64][65];
    if (blockIdx.x == 0 && blockIdx.y == 0 && threadIdx.x == 0) g_count = 0;
    int c0 = blockIdx.x * 64, d0 = blockIdx.y * 64;
    int a = threadIdx.x & 63, b = threadIdx.x >> 6;
    #pragma unroll
    for (int i = 0; i < 16; ++i) {
        int d = b + i * 4;
        ts[d][a] = embed[(size_t)(d0 + d) * NC + c0 + a];
    }
    __syncthreads();
    #pragma unroll
    for (int i = 0; i < 16; ++i) {
        int cI = b + i * 4;
        float v = ts[a][cI];
        size_t o = (size_t)(c0 + cI) * DIM + d0 + a;
        g_embedT[o] = v;
        g_ebh[o] = __float2half_rn(v);
    }
}

// ---------------------------------------------------------------------------
// K0b: 0.5*||e||^2
// ---------------------------------------------------------------------------
__global__ void prep_cnorm(void) {
    int w = threadIdx.x >> 5, l = threadIdx.x & 31;
    int c = blockIdx.x * 8 + w;
    const float4* er = reinterpret_cast<const float4*>(g_embedT + (size_t)c * DIM);
    float4 p = er[l], q = er[l + 32];
    float s = p.x*p.x + p.y*p.y + p.z*p.z + p.w*p.w
            + q.x*q.x + q.y*q.y + q.z*q.z + q.w*q.w;
    #pragma unroll
    for (int off = 16; off; off >>= 1) s += __shfl_down_sync(0xffffffffu, s, off);
    if (l == 0) g_cnh[c] = 0.5f * s;
}

// ---------------------------------------------------------------------------
// K0c: convert x -> fp16, pre-swizzled per 128-token tile (SM_A layout).
// ---------------------------------------------------------------------------
__global__ __launch_bounds__(256)
void prep_xconv(const float* __restrict__ x) {
    const int tile = blockIdx.x;
    const int w = threadIdx.x >> 5, l = threadIdx.x & 31;
    uint32_t* dst = reinterpret_cast<uint32_t*>(g_xh) + (size_t)tile * 16384;
    #pragma unroll
    for (int i = 0; i < 16; ++i) {
        int r = w + i * 8;
        const float2* xr2 = reinterpret_cast<const float2*>(
            x + ((size_t)tile * M_CTA + r) * DIM);
        #pragma unroll
        for (int kb = 0; kb < 4; ++kb) {
            float2 v = xr2[kb * 32 + l];
            __half h0 = __float2half_rn(v.x), h1 = __float2half_rn(v.y);
            uint32_t p = ((uint32_t)__half_as_ushort(h1) << 16) | __half_as_ushort(h0);
            dst[(kb * 16384 + swz((uint32_t)(r * 128 + l * 4))) >> 2] = p;
        }
    }
}

// ---------------------------------------------------------------------------
// K1: fp16 HMMA GEMM + per-split top-2 argmax.
//     3-stage B ring -> ONE barrier per k-step; running-pointer B loads.
// ---------------------------------------------------------------------------
__global__ __launch_bounds__(256, 2)
void vq_hmma(void) {
    extern __shared__ char smem[];
    const uint32_t sbase = smem_u32(smem);
    const int tid = threadIdx.x, lane = tid & 31, wid = tid >> 5;
    const int warp_m = wid & 3, warp_n = wid >> 2;
    const int tileId = blockIdx.x >> 1, split = blockIdx.x & 1;
    const int tokBase = tileId * M_CTA;
    const int codeBase = split * NC_S;

    const int seg = tid & 7, rb = tid >> 3;

    // running global pointer for B (stage base); +128 per kb, wrap per chunk
    const char* pB = reinterpret_cast<const char*>(g_ebh)
                   + ((size_t)(codeBase + rb) << 9) + seg * 16;
    // per-thread swizzled smem base (row-block i adds +4096, swizzle unaffected)
    const uint32_t sB0 = sbase + SM_B + swz((uint32_t)(rb * 128 + seg * 16));

    // A tile: straight 64KB async copy of pre-swizzled fp16 (group 0 w/ B stage 0)
    {
        const char* asrc = reinterpret_cast<const char*>(g_xh) + (size_t)tileId * 65536;
        #pragma unroll
        for (int k = 0; k < 16; ++k)
            cpa16(sbase + SM_A + tid * 16 + k * 4096, asrc + tid * 16 + k * 4096);
    }
    #pragma unroll
    for (int i = 0; i < 4; ++i) cpa16(sB0 + i * 4096, pB + i * 16384);
    CP_COMMIT();
    pB += 128;                               // kb 0 -> 1
    #pragma unroll
    for (int i = 0; i < 4; ++i) cpa16(sB0 + 16384 + i * 4096, pB + i * 16384);
    CP_COMMIT();
    pB += 128;                               // kb 1 -> 2

    float acc[2][8][4];
    float best[4], sec[4];
    int   bi[4];
    #pragma unroll
    for (int i = 0; i < 4; ++i) { best[i] = -1e30f; sec[i] = -1e30f; bi[i] = 0; }

    const int r16 = lane & 15, cg8 = (lane >> 4) << 3;
    int stW = 2, stR = 0;                    // write slot for j+2, read slot for j

    for (int j = 0; j < TOTJ_S; ++j) {
        if (j + 1 < TOTJ_S) CP_WAIT1(); else CP_WAIT0();
        __syncthreads();                     // stage j visible; stage stW free

        if (j + 2 < TOTJ_S) {
            uint32_t d = sB0 + stW * 16384;
            #pragma unroll
            for (int i = 0; i < 4; ++i) cpa16(d + i * 4096, pB + i * 16384);
            CP_COMMIT();
            pB += (((j + 2) & 3) == 3) ? (65536 - 384) : 128;
            stW = (stW == 2) ? 0 : stW + 1;
        }

        const int kb = j & 3;
        const uint32_t aB = sbase + SM_A + kb * 16384;
        const uint32_t bB = sbase + SM_B + stR * 16384;
        stR = (stR == 2) ? 0 : stR + 1;

        if (kb == 0) {
            #pragma unroll
            for (int mt = 0; mt < 2; ++mt)
                #pragma unroll
                for (int nt = 0; nt < 8; ++nt)
                    #pragma unroll
                    for (int e = 0; e < 4; ++e) acc[mt][nt][e] = 0.0f;
        }

        #pragma unroll
        for (int ks = 0; ks < 4; ++ks) {
            const int kcol = ks * 16 + cg8;
            uint32_t ah[2][4], bh[8][2];
            #pragma unroll
            for (int mt = 0; mt < 2; ++mt) {
                uint32_t off = swz((uint32_t)((warp_m * 32 + mt * 16 + r16) * 128 + kcol * 2));
                ldsm4(ah[mt], aB + off);
            }
            #pragma unroll
            for (int p = 0; p < 4; ++p) {
                uint32_t off = swz((uint32_t)((warp_n * 64 + p * 16 + r16) * 128 + kcol * 2));
                uint32_t t[4];
                ldsm4(t, bB + off);
                bh[2*p][0]   = t[0]; bh[2*p][1]   = t[2];
                bh[2*p+1][0] = t[1]; bh[2*p+1][1] = t[3];
            }
            #pragma unroll
            for (int mt = 0; mt < 2; ++mt)
                #pragma unroll
                for (int nt = 0; nt < 8; ++nt)
                    mma16816(acc[mt][nt], ah[mt], bh[nt]);
        }

        if (kb == 3) {
            const int c0 = codeBase + (j >> 2) * NCHUNK + warp_n * 64 + (lane & 3) * 2;
            #pragma unroll
            for (int nt = 0; nt < 8; ++nt) {
                const int col0 = c0 + nt * 8;
                const float cn0 = __ldg(&g_cnh[col0]);
                const float cn1 = __ldg(&g_cnh[col0 + 1]);
                #pragma unroll
                for (int mt = 0; mt < 2; ++mt) {
                    const int s0 = mt * 2, s1 = mt * 2 + 1;
                    float v;
                    v = acc[mt][nt][0] - cn0;
                    if (v > best[s0]) { sec[s0] = best[s0]; best[s0] = v; bi[s0] = col0; }
                    else if (v > sec[s0]) sec[s0] = v;
                    v = acc[mt][nt][1] - cn1;
                    if (v > best[s0]) { sec[s0] = best[s0]; best[s0] = v; bi[s0] = col0 + 1; }
                    else if (v > sec[s0]) sec[s0] = v;
                    v = acc[mt][nt][2] - cn0;
                    if (v > best[s1]) { sec[s1] = best[s1]; best[s1] = v; bi[s1] = col0; }
                    else if (v > sec[s1]) sec[s1] = v;
                    v = acc[mt][nt][3] - cn1;
                    if (v > best[s1]) { sec[s1] = best[s1]; best[s1] = v; bi[s1] = col0 + 1; }
                    else if (v > sec[s1]) sec[s1] = v;
                }
            }
        }
    }
    __syncthreads();                         // all compute done; SM_B reusable

    // intra-quad top-2 merge
    #pragma unroll
    for (int s = 0; s < 4; ++s) {
        float b = best[s], se = sec[s];
        int   i = bi[s];
        #pragma unroll
        for (int off = 1; off <= 2; off <<= 1) {
            float ob = __shfl_xor_sync(0xffffffffu, b, off);
            float os = __shfl_xor_sync(0xffffffffu, se, off);
            int   oi = __shfl_xor_sync(0xffffffffu, i, off);
            if (ob > b || (ob == b && oi < i)) { se = fmaxf(b, os); b = ob; i = oi; }
            else                               { se = fmaxf(se, ob); }
        }
        best[s] = b; sec[s] = se; bi[s] = i;
    }

    float* mb = reinterpret_cast<float*>(smem + SM_B);
    float* ms = mb + 128;
    int*   mi = reinterpret_cast<int*>(ms + 128);
    if (warp_n == 0 && (lane & 3) == 0) {
        #pragma unroll
        for (int s = 0; s < 4; ++s) {
            int row = warp_m * 32 + (s >> 1) * 16 + (s & 1) * 8 + (lane >> 2);
            mb[row] = best[s]; ms[row] = sec[s]; mi[row] = bi[s];
        }
    }
    __syncthreads();
    if (warp_n == 1 && (lane & 3) == 0) {
        #pragma unroll
        for (int s = 0; s < 4; ++s) {
            int row = warp_m * 32 + (s >> 1) * 16 + (s & 1) * 8 + (lane >> 2);
            float b = best[s], se = sec[s];
            int   i = bi[s];
            float ob = mb[row], os = ms[row];
            int   oi = mi[row];
            if (ob > b || (ob == b && oi < i)) { se = fmaxf(b, os); b = ob; i = oi; }
            else                               { se = fmaxf(se, ob); }
            size_t o = (size_t)split * N_TOK + tokBase + row;
            g_hb[o] = b; g_hs[o] = se; g_hi[o] = i;
        }
    }
}

// ---------------------------------------------------------------------------
// K1b: merge the two code-half results -> winner, margin flag, compaction
// ---------------------------------------------------------------------------
__global__ void merge_halves(void) {
    int t = blockIdx.x * 256 + threadIdx.x;
    float b0 = g_hb[t], b1 = g_hb[N_TOK + t];
    float s0 = g_hs[t], s1 = g_hs[N_TOK + t];
    int   i0 = g_hi[t], i1 = g_hi[N_TOK + t];
    float b, se; int i;
    if (b1 > b0 || (b1 == b0 && i1 < i0)) { b = b1; i = i1; se = fmaxf(s1, b0); }
    else                                  { b = b0; i = i0; se = fmaxf(s0, b1); }
    if (b - se < MARGIN) {
        g_idx[t]  = ~i;
        g_best[t] = 0ULL;
        int p = atomicAdd(&g_count, 1);
        g_list[p] = t;
    } else {
        g_idx[t] = i;
    }
}

// ---------------------------------------------------------------------------
// K2: exact fp32 rescore — persistent grid. Task = (8 tokens) x (512 codes).
// ---------------------------------------------------------------------------
__global__ __launch_bounds__(256)
void fixup_micro(const float* __restrict__ x, const float* __restrict__ embed) {
    extern __shared__ char fsm[];
    const uint32_t fbase = smem_u32(fsm);
    float (*Es)[8][512] = reinterpret_cast<float(*)[8][512]>(fsm + FX_ES);
    float (*Xs)[256]    = reinterpret_cast<float(*)[256]>(fsm + FX_XS);
    int*   toks         = reinterpret_cast<int*>(fsm + FX_TOKS);
    float (*wb)[8]      = reinterpret_cast<float(*)[8]>(fsm + FX_WB);
    int   (*wi)[8]      = reinterpret_cast<int(*)[8]>(fsm + FX_WI);

    const int tid = threadIdx.x, lane = tid & 31, wid = tid >> 5;
    const int cnt = g_count;
    const int nTasks = ((cnt + 7) >> 3) * 8;

    for (int task = blockIdx.x; task < nTasks; task += FX_GRID) {
        const int grp = task >> 3, part = task & 7;
        const int cbase = part * 512;

        __syncthreads();                 // protect smem reuse across tasks
        if (tid < 8) {
            int li = grp * 8 + tid;
            toks[tid] = g_list[li < cnt ? li : 0];
        }
        __syncthreads();
        {
            int tk = tid & 7, d0 = (tid >> 3) * 8;
            const float* xr = x + (size_t)toks[tk] * DIM + d0;
            #pragma unroll
            for (int i = 0; i < 8; ++i) Xs[tk][d0 + i] = xr[i];
        }

        auto loadE = [&](int s) {
            uint32_t dst = fbase + FX_ES + (s % 3) * 16384 + wid * 2048 + lane * 16;
            const float* src = embed + (size_t)(s * 8 + wid) * NC + cbase + lane * 4;
            #pragma unroll
            for (int r = 0; r < 4; ++r) cpa16(dst + r * 512, src + r * 128);
        };
        loadE(0); CP_COMMIT();
        loadE(1); CP_COMMIT();

        float acc[8][2];
        #pragma unroll
        for (int t = 0; t < 8; ++t) { acc[t][0] = 0.0f; acc[t][1] = 0.0f; }

        for (int s = 0; s < 32; ++s) {
            if (s < 30) CP_WAIT1(); else CP_WAIT0();
            __syncthreads();
            if (s + 2 < 32) { loadE(s + 2); CP_COMMIT(); }

            const int buf = s % 3;
            #pragma unroll
            for (int h = 0; h < 2; ++h) {
                float4 xq[8];
                #pragma unroll
                for (int t = 0; t < 8; ++t)
                    xq[t] = *reinterpret_cast<const float4*>(&Xs[t][s * 8 + h * 4]);
                #pragma unroll
                for (int k2 = 0; k2 < 4; ++k2) {
                    float2 e2 = *reinterpret_cast<const float2*>(
                        &Es[buf][h * 4 + k2][tid * 2]);
                    #pragma unroll
                    for (int t = 0; t < 8; ++t) {
                        float xv = (k2 == 0) ? xq[t].x : (k2 == 1) ? xq[t].y
                                 : (k2 == 2) ? xq[t].z : xq[t].w;
                        acc[t][0] = fmaf(xv, e2.x, acc[t][0]);
                        acc[t][1] = fmaf(xv, e2.y, acc[t][1]);
                    }
                }
            }
        }

        float best[8]; int bi[8];
        #pragma unroll
        for (int t = 0; t < 8; ++t) { best[t] = -1e30f; bi[t] = 0; }
        #pragma unroll
        for (int jj = 0; jj < 2; ++jj) {
            int c = cbase + tid * 2 + jj;
            float cn = g_cnh[c];
            #pragma unroll
            for (int t = 0; t < 8; ++t) {
                float s = acc[t][jj] - cn;
                if (s > best[t]) { best[t] = s; bi[t] = c; }
            }
        }

        #pragma unroll
        for (int t = 0; t < 8; ++t) {
            float b = best[t]; int i = bi[t];
            #pragma unroll
            for (int off = 16; off; off >>= 1) {
                float ob = __shfl_down_sync(0xffffffffu, b, off);
                int   oi = __shfl_down_sync(0xffffffffu, i, off);
                if (ob > b || (ob == b && oi < i)) { b = ob; i = oi; }
            }
            if (lane == 0) { wb[wid][t] = b; wi[wid][t] = i; }
        }
        __syncthreads();
        if (wid == 0 && lane < 8) {
            int t = lane;
            float b = wb[0][t]; int i = wi[0][t];
            #pragma unroll
            for (int w = 1; w < 8; ++w) {
                float ob = wb[w][t]; int oi = wi[w][t];
                if (ob > b || (ob == b && oi < i)) { b = ob; i = oi; }
            }
            atomicMax(&g_best[toks[t]], pack_si(b, i));
        }
    }
}

// ---------------------------------------------------------------------------
// K3: gather quantize + per-CTA diff partial + indices (warp per token)
// ---------------------------------------------------------------------------
__global__ __launch_bounds__(256)
void quantize_kernel(const float* __restrict__ x, float* __restrict__ out) {
    __shared__ float swred[8];
    int gt = blockIdx.x * 8 + (threadIdx.x >> 5);
    int l = threadIdx.x & 31, wid = threadIdx.x >> 5;
    int idx = g_idx[gt];
    if (idx < 0)
        idx = NC - 1 - (int)(uint32_t)(g_best[gt] & 0xFFFFFFFFULL);
    const float4* er = reinterpret_cast<const float4*>(g_embedT + (size_t)idx * DIM);
    const float4* xr = reinterpret_cast<const float4*>(x + (size_t)gt * DIM);
    float4* qw = reinterpret_cast<float4*>(out + (size_t)gt * DIM);
    float s = 0.0f;
    #pragma unroll
    for (int i = 0; i < 2; ++i) {
        int k = l + 32 * i;
        float4 q = er[k], xv = xr[k];
        float d0 = q.x - xv.x, d1 = q.y - xv.y, d2 = q.z - xv.z, d3 = q.w - xv.w;
        s = fmaf(d0, d0, s); s = fmaf(d1, d1, s);
        s = fmaf(d2, d2, s); s = fmaf(d3, d3, s);
        qw[k] = q;
    }
    #pragma unroll
    for (int off = 16; off; off >>= 1) s += __shfl_down_sync(0xffffffffu, s, off);
    if (l == 0) {
        swred[wid] = s;
        out[QELEMS + 1 + (size_t)gt] = (float)idx;
    }
    __syncthreads();
    if (threadIdx.x == 0) {
        float tot = 0.0f;
        #pragma unroll
        for (int w = 0; w < 8; ++w) tot += swred[w];
        g_partials[blockIdx.x] = tot;
    }
}

// ---------------------------------------------------------------------------
// K4: deterministic diff reduction (8192 per-CTA partials)
// ---------------------------------------------------------------------------
__global__ void finalize_kernel(float* __restrict__ out) {
    __shared__ float sh[256];
    int tid = threadIdx.x;
    const float4* p4 = reinterpret_cast<const float4*>(g_partials);
    float s = 0.0f;
    #pragma unroll
    for (int j = 0; j < 8; ++j) {
        float4 v = p4[tid + 256 * j];
        s += v.x + v.y + v.z + v.w;
    }
    sh[tid] = s;
    __syncthreads();
    for (int off = 128; off; off >>= 1) {
        if (tid < off) sh[tid] += sh[tid + off];
        __syncthreads();
    }
    if (tid == 0) out[QELEMS] = sh[0] / (float)QELEMS;
}

// ---------------------------------------------------------------------------
extern "C" void kernel_launch(void* const* d_in, const int* in_sizes, int n_in,
                              void* d_out, int out_size) {
    const float* x     = (const float*)d_in[0];
    const float* embed = (const float*)d_in[1];
    float* out = (float*)d_out;

    cudaFuncSetAttribute(vq_hmma, cudaFuncAttributeMaxDynamicSharedMemorySize,
                         SMEM_TOTAL);
    cudaFuncSetAttribute(fixup_micro, cudaFuncAttributeMaxDynamicSharedMemorySize,
                         FX_SMEM);

    prep_transpose<<<dim3(NC / 64, DIM / 64), 256>>>(embed);
    prep_cnorm<<<NC / 8, 256>>>();
    prep_xconv<<<NTILES, 256>>>(x);
    vq_hmma<<<K1_GRID, 256, SMEM_TOTAL>>>();
    merge_halves<<<N_TOK / 256, 256>>>();
    fixup_micro<<<FX_GRID, 256, FX_SMEM>>>(x, embed);
    quantize_kernel<<<N_TOK / 8, 256>>>(x, out);
    finalize_kernel<<<1, 256>>>(out);
}

// round 15
// speedup vs baseline: 1.0529x; 1.0106x over previous
#include <cuda_runtime.h>
#include <cuda_fp16.h>
#include <cstdint>

#define N_TOK   65536
#define DIM     256
#define NC      4096
#define QELEMS  ((size_t)N_TOK * DIM)

#define M_CTA    128
#define NCHUNK   128
#define NSPLIT   2
#define NC_S     (NC / NSPLIT)          // 2048 codes per split CTA
#define NCHUNKS_S (NC_S / NCHUNK)       // 16
#define TOTJ_S   (NCHUNKS_S * 4)        // 64 k-block steps
#define NTILES   (N_TOK / M_CTA)        // 512
#define K1_GRID  (NTILES * NSPLIT)      // 1024
#define MARGIN   0.03f

// K1 dynamic smem layout (bytes) — A + 3-stage B ring, 2 CTAs/SM
#define SM_A     0                       // 128x256 fp16 = 65536
#define SM_B     65536                   // 3 stages x 16KB = 49152
#define SMEM_TOTAL (SM_B + 49152)        // 114688

// fixup dynamic smem: 3-stage Es ring (512 codes/task) + Xs + small
#define FX_ES     0                      // 3 x 8 x 512 f32 = 49152
#define FX_XS     49152                  // 8 x 256 f32 = 8192
#define FX_TOKS   (FX_XS + 8192)         // 8 ints
#define FX_WB     (FX_TOKS + 32)         // 8x8 f32
#define FX_WI     (FX_WB + 256)          // 8x8 int
#define FX_SMEM   (FX_WI + 256)          // 57888
#define FX_GRID   1184

// -------------------- scratch ----------------------------------------------
__device__ __half g_ebh[(size_t)NC * DIM];          // fp16 codebook [code][dim]
__device__ __half g_xh[(size_t)N_TOK * DIM];        // fp16 x, pre-swizzled per tile
__device__ float  g_embedT[(size_t)NC * DIM];       // fp32 codebook [code][dim]
__device__ float  g_cnh[NC];                        // 0.5*||e||^2
__device__ int    g_idx[N_TOK];                     // winner; ~i if flagged
__device__ float  g_partials[N_TOK / 8];            // per-CTA diff partials
__device__ int    g_count;
__device__ int    g_list[N_TOK];
__device__ unsigned long long g_best[N_TOK];
// per-split K1 results
__device__ float  g_hb[NSPLIT * N_TOK];
__device__ float  g_hs[NSPLIT * N_TOK];
__device__ int    g_hi[NSPLIT * N_TOK];

// -------------------- helpers ----------------------------------------------
__device__ __forceinline__ uint32_t smem_u32(const void* p) {
    uint32_t a;
    asm("{ .reg .u64 t; cvta.to.shared.u64 t, %1; cvt.u32.u64 %0, t; }"
        : "=r"(a) : "l"(p));
    return a;
}
__device__ __forceinline__ uint32_t swz(uint32_t b) { return b ^ ((b >> 3) & 0x70); }

__device__ __forceinline__ void ldsm4(uint32_t* r, uint32_t a) {
    asm volatile("ldmatrix.sync.aligned.m8n8.x4.shared.b16 {%0,%1,%2,%3}, [%4];"
        : "=r"(r[0]), "=r"(r[1]), "=r"(r[2]), "=r"(r[3]) : "r"(a));
}
__device__ __forceinline__ void mma16816(float* c, const uint32_t* a, const uint32_t* b) {
    asm volatile("mma.sync.aligned.m16n8k16.row.col.f32.f16.f16.f32 "
        "{%0,%1,%2,%3}, {%4,%5,%6,%7}, {%8,%9}, {%0,%1,%2,%3};"
        : "+f"(c[0]), "+f"(c[1]), "+f"(c[2]), "+f"(c[3])
        : "r"(a[0]), "r"(a[1]), "r"(a[2]), "r"(a[3]), "r"(b[0]), "r"(b[1]));
}
__device__ __forceinline__ void cpa16(uint32_t s, const void* g) {
    asm volatile("cp.async.cg.shared.global [%0], [%1], 16;" :: "r"(s), "l"(g));
}
#define CP_COMMIT() asm volatile("cp.async.commit_group;" ::: "memory")
#define CP_WAIT1()  asm volatile("cp.async.wait_group 1;" ::: "memory")
#define CP_WAIT0()  asm volatile("cp.async.wait_group 0;" ::: "memory")

// monotonic (score, smaller-idx-wins) packing for atomicMax merge
__device__ __forceinline__ unsigned long long pack_si(float s, int idx) {
    uint32_t u = __float_as_uint(s);
    u = (s < 0.0f) ? ~u : (u | 0x80000000u);
    return ((unsigned long long)u << 32) | (uint32_t)(NC - 1 - idx);
}

// ---------------------------------------------------------------------------
// K0a: transpose codebook + fp16 cast; zero compaction counter
// ---------------------------------------------------------------------------
__global__ void prep_transpose(const float* __restrict__ embed) {
    __shared__ float ts[64][65];
    if (blockIdx.x == 0 && blockIdx.y == 0 && threadIdx.x == 0) g_count = 0;
    int c0 = blockIdx.x * 64, d0 = blockIdx.y * 64;
    int a = threadIdx.x & 63, b = threadIdx.x >> 6;
    #pragma unroll
    for (int i = 0; i < 16; ++i) {
        int d = b + i * 4;
        ts[d][a] = embed[(size_t)(d0 + d) * NC + c0 + a];
    }
    __syncthreads();
    #pragma unroll
    for (int i = 0; i < 16; ++i) {
        int cI = b + i * 4;
        float v = ts[a][cI];
        size_t o = (size_t)(c0 + cI) * DIM + d0 + a;
        g_embedT[o] = v;
        g_ebh[o] = __float2half_rn(v);
    }
}

// ---------------------------------------------------------------------------
// K0b: 0.5*||e||^2
// ---------------------------------------------------------------------------
__global__ void prep_cnorm(void) {
    int w = threadIdx.x >> 5, l = threadIdx.x & 31;
    int c = blockIdx.x * 8 + w;
    const float4* er = reinterpret_cast<const float4*>(g_embedT + (size_t)c * DIM);
    float4 p = er[l], q = er[l + 32];
    float s = p.x*p.x + p.y*p.y + p.z*p.z + p.w*p.w
            + q.x*q.x + q.y*q.y + q.z*q.z + q.w*q.w;
    #pragma unroll
    for (int off = 16; off; off >>= 1) s += __shfl_down_sync(0xffffffffu, s, off);
    if (l == 0) g_cnh[c] = 0.5f * s;
}

// ---------------------------------------------------------------------------
// K0c: convert x -> fp16, pre-swizzled per 128-token tile (SM_A layout).
// ---------------------------------------------------------------------------
__global__ __launch_bounds__(256)
void prep_xconv(const float* __restrict__ x) {
    const int tile = blockIdx.x;
    const int w = threadIdx.x >> 5, l = threadIdx.x & 31;
    uint32_t* dst = reinterpret_cast<uint32_t*>(g_xh) + (size_t)tile * 16384;
    #pragma unroll
    for (int i = 0; i < 16; ++i) {
        int r = w + i * 8;
        const float2* xr2 = reinterpret_cast<const float2*>(
            x + ((size_t)tile * M_CTA + r) * DIM);
        #pragma unroll
        for (int kb = 0; kb < 4; ++kb) {
            float2 v = xr2[kb * 32 + l];
            __half h0 = __float2half_rn(v.x), h1 = __float2half_rn(v.y);
            uint32_t p = ((uint32_t)__half_as_ushort(h1) << 16) | __half_as_ushort(h0);
            dst[(kb * 16384 + swz((uint32_t)(r * 128 + l * 4))) >> 2] = p;
        }
    }
}

// ---------------------------------------------------------------------------
// K1: fp16 HMMA GEMM + per-split top-2 argmax.
//     3-stage B ring, one barrier per k-step, fully hoisted LDSM addressing:
//     swz(row*128+col) = row*128 + (col ^ ((r16&7)<<4)) since all other row
//     terms are multiples of 8 -> 10 per-thread address constants.
// ---------------------------------------------------------------------------
__global__ __launch_bounds__(256, 2)
void vq_hmma(void) {
    extern __shared__ char smem[];
    const uint32_t sbase = smem_u32(smem);
    const int tid = threadIdx.x, lane = tid & 31, wid = tid >> 5;
    const int warp_m = wid & 3, warp_n = wid >> 2;
    const int tileId = blockIdx.x >> 1, split = blockIdx.x & 1;
    const int tokBase = tileId * M_CTA;
    const int codeBase = split * NC_S;

    const int seg = tid & 7, rb = tid >> 3;

    // running global pointer for B (stage base); +128 per kb, wrap per chunk
    const char* pB = reinterpret_cast<const char*>(g_ebh)
                   + ((size_t)(codeBase + rb) << 9) + seg * 16;
    const uint32_t sB0 = sbase + SM_B + swz((uint32_t)(rb * 128 + seg * 16));

    // A tile: straight 64KB async copy of pre-swizzled fp16 (group 0 w/ B stage 0)
    {
        const char* asrc = reinterpret_cast<const char*>(g_xh) + (size_t)tileId * 65536;
        #pragma unroll
        for (int k = 0; k < 16; ++k)
            cpa16(sbase + SM_A + tid * 16 + k * 4096, asrc + tid * 16 + k * 4096);
    }
    #pragma unroll
    for (int i = 0; i < 4; ++i) cpa16(sB0 + i * 4096, pB + i * 16384);
    CP_COMMIT();
    pB += 128;                               // kb 0 -> 1
    #pragma unroll
    for (int i = 0; i < 4; ++i) cpa16(sB0 + 16384 + i * 4096, pB + i * 16384);
    CP_COMMIT();
    pB += 128;                               // kb 1 -> 2

    float acc[2][8][4];
    float best[4], sec[4];
    int   bi[4];
    #pragma unroll
    for (int i = 0; i < 4; ++i) { best[i] = -1e30f; sec[i] = -1e30f; bi[i] = 0; }

    const int r16 = lane & 15;

    // ---- precomputed LDSM address components (bit-identical to swz form) ----
    const uint32_t cmask = (uint32_t)((r16 & 7) << 4);
    uint32_t colx[4];
    #pragma unroll
    for (int ks = 0; ks < 4; ++ks)
        colx[ks] = (uint32_t)((ks * 32 + ((lane >> 4) << 4)) ^ cmask);
    uint32_t aRow[2], bRow[4];
    #pragma unroll
    for (int mt = 0; mt < 2; ++mt)
        aRow[mt] = sbase + SM_A + (uint32_t)((warp_m * 32 + mt * 16 + r16) * 128);
    #pragma unroll
    for (int p = 0; p < 4; ++p)
        bRow[p] = sbase + SM_B + (uint32_t)((warp_n * 64 + p * 16 + r16) * 128);

    int stW = 2, stR = 0;                    // write slot for j+2, read slot for j

    for (int j = 0; j < TOTJ_S; ++j) {
        if (j + 1 < TOTJ_S) CP_WAIT1(); else CP_WAIT0();
        __syncthreads();                     // stage j visible; stage stW free

        if (j + 2 < TOTJ_S) {
            uint32_t d = sB0 + stW * 16384;
            #pragma unroll
            for (int i = 0; i < 4; ++i) cpa16(d + i * 4096, pB + i * 16384);
            CP_COMMIT();
            pB += (((j + 2) & 3) == 3) ? (65536 - 384) : 128;
            stW = (stW == 2) ? 0 : stW + 1;
        }

        const int kb = j & 3;
        const uint32_t aOff = (uint32_t)(kb * 16384);
        const uint32_t bOff = (uint32_t)(stR * 16384);
        stR = (stR == 2) ? 0 : stR + 1;

        if (kb == 0) {
            #pragma unroll
            for (int mt = 0; mt < 2; ++mt)
                #pragma unroll
                for (int nt = 0; nt < 8; ++nt)
                    #pragma unroll
                    for (int e = 0; e < 4; ++e) acc[mt][nt][e] = 0.0f;
        }

        #pragma unroll
        for (int ks = 0; ks < 4; ++ks) {
            const uint32_t cx = colx[ks];
            uint32_t ah[2][4], bh[8][2];
            #pragma unroll
            for (int mt = 0; mt < 2; ++mt)
                ldsm4(ah[mt], aRow[mt] + aOff + cx);
            #pragma unroll
            for (int p = 0; p < 4; ++p) {
                uint32_t t[4];
                ldsm4(t, bRow[p] + bOff + cx);
                bh[2*p][0]   = t[0]; bh[2*p][1]   = t[2];
                bh[2*p+1][0] = t[1]; bh[2*p+1][1] = t[3];
            }
            #pragma unroll
            for (int mt = 0; mt < 2; ++mt)
                #pragma unroll
                for (int nt = 0; nt < 8; ++nt)
                    mma16816(acc[mt][nt], ah[mt], bh[nt]);
        }

        if (kb == 3) {
            const int c0 = codeBase + (j >> 2) * NCHUNK + warp_n * 64 + (lane & 3) * 2;
            #pragma unroll
            for (int nt = 0; nt < 8; ++nt) {
                const int col0 = c0 + nt * 8;
                const float cn0 = __ldg(&g_cnh[col0]);
                const float cn1 = __ldg(&g_cnh[col0 + 1]);
                #pragma unroll
                for (int mt = 0; mt < 2; ++mt) {
                    const int s0 = mt * 2, s1 = mt * 2 + 1;
                    float v;
                    v = acc[mt][nt][0] - cn0;
                    if (v > best[s0]) { sec[s0] = best[s0]; best[s0] = v; bi[s0] = col0; }
                    else if (v > sec[s0]) sec[s0] = v;
                    v = acc[mt][nt][1] - cn1;
                    if (v > best[s0]) { sec[s0] = best[s0]; best[s0] = v; bi[s0] = col0 + 1; }
                    else if (v > sec[s0]) sec[s0] = v;
                    v = acc[mt][nt][2] - cn0;
                    if (v > best[s1]) { sec[s1] = best[s1]; best[s1] = v; bi[s1] = col0; }
                    else if (v > sec[s1]) sec[s1] = v;
                    v = acc[mt][nt][3] - cn1;
                    if (v > best[s1]) { sec[s1] = best[s1]; best[s1] = v; bi[s1] = col0 + 1; }
                    else if (v > sec[s1]) sec[s1] = v;
                }
            }
        }
    }
    __syncthreads();                         // all compute done; SM_B reusable

    // intra-quad top-2 merge
    #pragma unroll
    for (int s = 0; s < 4; ++s) {
        float b = best[s], se = sec[s];
        int   i = bi[s];
        #pragma unroll
        for (int off = 1; off <= 2; off <<= 1) {
            float ob = __shfl_xor_sync(0xffffffffu, b, off);
            float os = __shfl_xor_sync(0xffffffffu, se, off);
            int   oi = __shfl_xor_sync(0xffffffffu, i, off);
            if (ob > b || (ob == b && oi < i)) { se = fmaxf(b, os); b = ob; i = oi; }
            else                               { se = fmaxf(se, ob); }
        }
        best[s] = b; sec[s] = se; bi[s] = i;
    }

    float* mb = reinterpret_cast<float*>(smem + SM_B);
    float* ms = mb + 128;
    int*   mi = reinterpret_cast<int*>(ms + 128);
    if (warp_n == 0 && (lane & 3) == 0) {
        #pragma unroll
        for (int s = 0; s < 4; ++s) {
            int row = warp_m * 32 + (s >> 1) * 16 + (s & 1) * 8 + (lane >> 2);
            mb[row] = best[s]; ms[row] = sec[s]; mi[row] = bi[s];
        }
    }
    __syncthreads();
    if (warp_n == 1 && (lane & 3) == 0) {
        #pragma unroll
        for (int s = 0; s < 4; ++s) {
            int row = warp_m * 32 + (s >> 1) * 16 + (s & 1) * 8 + (lane >> 2);
            float b = best[s], se = sec[s];
            int   i = bi[s];
            float ob = mb[row], os = ms[row];
            int   oi = mi[row];
            if (ob > b || (ob == b && oi < i)) { se = fmaxf(b, os); b = ob; i = oi; }
            else                               { se = fmaxf(se, ob); }
            size_t o = (size_t)split * N_TOK + tokBase + row;
            g_hb[o] = b; g_hs[o] = se; g_hi[o] = i;
        }
    }
}

// ---------------------------------------------------------------------------
// K1b: merge the two code-half results -> winner, margin flag, compaction
// ---------------------------------------------------------------------------
__global__ void merge_halves(void) {
    int t = blockIdx.x * 256 + threadIdx.x;
    float b0 = g_hb[t], b1 = g_hb[N_TOK + t];
    float s0 = g_hs[t], s1 = g_hs[N_TOK + t];
    int   i0 = g_hi[t], i1 = g_hi[N_TOK + t];
    float b, se; int i;
    if (b1 > b0 || (b1 == b0 && i1 < i0)) { b = b1; i = i1; se = fmaxf(s1, b0); }
    else                                  { b = b0; i = i0; se = fmaxf(s0, b1); }
    if (b - se < MARGIN) {
        g_idx[t]  = ~i;
        g_best[t] = 0ULL;
        int p = atomicAdd(&g_count, 1);
        g_list[p] = t;
    } else {
        g_idx[t] = i;
    }
}

// ---------------------------------------------------------------------------
// K2: exact fp32 rescore — persistent grid. Task = (8 tokens) x (512 codes).
// ---------------------------------------------------------------------------
__global__ __launch_bounds__(256)
void fixup_micro(const float* __restrict__ x, const float* __restrict__ embed) {
    extern __shared__ char fsm[];
    const uint32_t fbase = smem_u32(fsm);
    float (*Es)[8][512] = reinterpret_cast<float(*)[8][512]>(fsm + FX_ES);
    float (*Xs)[256]    = reinterpret_cast<float(*)[256]>(fsm + FX_XS);
    int*   toks         = reinterpret_cast<int*>(fsm + FX_TOKS);
    float (*wb)[8]      = reinterpret_cast<float(*)[8]>(fsm + FX_WB);
    int   (*wi)[8]      = reinterpret_cast<int(*)[8]>(fsm + FX_WI);

    const int tid = threadIdx.x, lane = tid & 31, wid = tid >> 5;
    const int cnt = g_count;
    const int nTasks = ((cnt + 7) >> 3) * 8;

    for (int task = blockIdx.x; task < nTasks; task += FX_GRID) {
        const int grp = task >> 3, part = task & 7;
        const int cbase = part * 512;

        __syncthreads();                 // protect smem reuse across tasks
        if (tid < 8) {
            int li = grp * 8 + tid;
            toks[tid] = g_list[li < cnt ? li : 0];
        }
        __syncthreads();
        {
            int tk = tid & 7, d0 = (tid >> 3) * 8;
            const float* xr = x + (size_t)toks[tk] * DIM + d0;
            #pragma unroll
            for (int i = 0; i < 8; ++i) Xs[tk][d0 + i] = xr[i];
        }

        auto loadE = [&](int s) {
            uint32_t dst = fbase + FX_ES + (s % 3) * 16384 + wid * 2048 + lane * 16;
            const float* src = embed + (size_t)(s * 8 + wid) * NC + cbase + lane * 4;
            #pragma unroll
            for (int r = 0; r < 4; ++r) cpa16(dst + r * 512, src + r * 128);
        };
        loadE(0); CP_COMMIT();
        loadE(1); CP_COMMIT();

        float acc[8][2];
        #pragma unroll
        for (int t = 0; t < 8; ++t) { acc[t][0] = 0.0f; acc[t][1] = 0.0f; }

        for (int s = 0; s < 32; ++s) {
            if (s < 30) CP_WAIT1(); else CP_WAIT0();
            __syncthreads();
            if (s + 2 < 32) { loadE(s + 2); CP_COMMIT(); }

            const int buf = s % 3;
            #pragma unroll
            for (int h = 0; h < 2; ++h) {
                float4 xq[8];
                #pragma unroll
                for (int t = 0; t < 8; ++t)
                    xq[t] = *reinterpret_cast<const float4*>(&Xs[t][s * 8 + h * 4]);
                #pragma unroll
                for (int k2 = 0; k2 < 4; ++k2) {
                    float2 e2 = *reinterpret_cast<const float2*>(
                        &Es[buf][h * 4 + k2][tid * 2]);
                    #pragma unroll
                    for (int t = 0; t < 8; ++t) {
                        float xv = (k2 == 0) ? xq[t].x : (k2 == 1) ? xq[t].y
                                 : (k2 == 2) ? xq[t].z : xq[t].w;
                        acc[t][0] = fmaf(xv, e2.x, acc[t][0]);
                        acc[t][1] = fmaf(xv, e2.y, acc[t][1]);
                    }
                }
            }
        }

        float best[8]; int bi[8];
        #pragma unroll
        for (int t = 0; t < 8; ++t) { best[t] = -1e30f; bi[t] = 0; }
        #pragma unroll
        for (int jj = 0; jj < 2; ++jj) {
            int c = cbase + tid * 2 + jj;
            float cn = g_cnh[c];
            #pragma unroll
            for (int t = 0; t < 8; ++t) {
                float s = acc[t][jj] - cn;
                if (s > best[t]) { best[t] = s; bi[t] = c; }
            }
        }

        #pragma unroll
        for (int t = 0; t < 8; ++t) {
            float b = best[t]; int i = bi[t];
            #pragma unroll
            for (int off = 16; off; off >>= 1) {
                float ob = __shfl_down_sync(0xffffffffu, b, off);
                int   oi = __shfl_down_sync(0xffffffffu, i, off);
                if (ob > b || (ob == b && oi < i)) { b = ob; i = oi; }
            }
            if (lane == 0) { wb[wid][t] = b; wi[wid][t] = i; }
        }
        __syncthreads();
        if (wid == 0 && lane < 8) {
            int t = lane;
            float b = wb[0][t]; int i = wi[0][t];
            #pragma unroll
            for (int w = 1; w < 8; ++w) {
                float ob = wb[w][t]; int oi = wi[w][t];
                if (ob > b || (ob == b && oi < i)) { b = ob; i = oi; }
            }
            atomicMax(&g_best[toks[t]], pack_si(b, i));
        }
    }
}

// ---------------------------------------------------------------------------
// K3: gather quantize + per-CTA diff partial + indices (warp per token)
// ---------------------------------------------------------------------------
__global__ __launch_bounds__(256)
void quantize_kernel(const float* __restrict__ x, float* __restrict__ out) {
    __shared__ float swred[8];
    int gt = blockIdx.x * 8 + (threadIdx.x >> 5);
    int l = threadIdx.x & 31, wid = threadIdx.x >> 5;
    int idx = g_idx[gt];
    if (idx < 0)
        idx = NC - 1 - (int)(uint32_t)(g_best[gt] & 0xFFFFFFFFULL);
    const float4* er = reinterpret_cast<const float4*>(g_embedT + (size_t)idx * DIM);
    const float4* xr = reinterpret_cast<const float4*>(x + (size_t)gt * DIM);
    float4* qw = reinterpret_cast<float4*>(out + (size_t)gt * DIM);
    float s = 0.0f;
    #pragma unroll
    for (int i = 0; i < 2; ++i) {
        int k = l + 32 * i;
        float4 q = er[k], xv = xr[k];
        float d0 = q.x - xv.x, d1 = q.y - xv.y, d2 = q.z - xv.z, d3 = q.w - xv.w;
        s = fmaf(d0, d0, s); s = fmaf(d1, d1, s);
        s = fmaf(d2, d2, s); s = fmaf(d3, d3, s);
        qw[k] = q;
    }
    #pragma unroll
    for (int off = 16; off; off >>= 1) s += __shfl_down_sync(0xffffffffu, s, off);
    if (l == 0) {
        swred[wid] = s;
        out[QELEMS + 1 + (size_t)gt] = (float)idx;
    }
    __syncthreads();
    if (threadIdx.x == 0) {
        float tot = 0.0f;
        #pragma unroll
        for (int w = 0; w < 8; ++w) tot += swred[w];
        g_partials[blockIdx.x] = tot;
    }
}

// ---------------------------------------------------------------------------
// K4: deterministic diff reduction (8192 per-CTA partials)
// ---------------------------------------------------------------------------
__global__ void finalize_kernel(float* __restrict__ out) {
    __shared__ float sh[256];
    int tid = threadIdx.x;
    const float4* p4 = reinterpret_cast<const float4*>(g_partials);
    float s = 0.0f;
    #pragma unroll
    for (int j = 0; j < 8; ++j) {
        float4 v = p4[tid + 256 * j];
        s += v.x + v.y + v.z + v.w;
    }
    sh[tid] = s;
    __syncthreads();
    for (int off = 128; off; off >>= 1) {
        if (tid < off) sh[tid] += sh[tid + off];
        __syncthreads();
    }
    if (tid == 0) out[QELEMS] = sh[0] / (float)QELEMS;
}

// ---------------------------------------------------------------------------
extern "C" void kernel_launch(void* const* d_in, const int* in_sizes, int n_in,
                              void* d_out, int out_size) {
    const float* x     = (const float*)d_in[0];
    const float* embed = (const float*)d_in[1];
    float* out = (float*)d_out;

    cudaFuncSetAttribute(vq_hmma, cudaFuncAttributeMaxDynamicSharedMemorySize,
                         SMEM_TOTAL);
    cudaFuncSetAttribute(fixup_micro, cudaFuncAttributeMaxDynamicSharedMemorySize,
                         FX_SMEM);

    prep_transpose<<<dim3(NC / 64, DIM / 64), 256>>>(embed);
    prep_cnorm<<<NC / 8, 256>>>();
    prep_xconv<<<NTILES, 256>>>(x);
    vq_hmma<<<K1_GRID, 256, SMEM_TOTAL>>>();
    merge_halves<<<N_TOK / 256, 256>>>();
    fixup_micro<<<FX_GRID, 256, FX_SMEM>>>(x, embed);
    quantize_kernel<<<N_TOK / 8, 256>>>(x, out);
    finalize_kernel<<<1, 256>>>(out);
}